// round 11
// baseline (speedup 1.0000x reference)
#include <cuda_runtime.h>
#include <cuda_bf16.h>
#include <cstdint>
#include <cstddef>

// B=4, N=256, E=512. Persistent kernel, 296 CTAs x 128 threads, phases:
//   P0: split X, X^T, Qw, Kw^T into bf16 hi/lo planes
//   P1: G = X X^T          (32x64 lower tiles, K=512, 80 jobs)
//   P2: S = L( L(G) Kw )   (80 jobs, K<=i)
//   P3: T = L( S Qw^T )    (80 jobs)
//   P4: F = T X            (256 jobs, fp32 out)
//   P5: out = x*(1+f-x.f)  (1024 jobs)
// GEMM engine: mma.sync.m16n8k16 bf16 with 2-way split operands
// (D += Ah*Bh + Ah*Bl + Al*Bh), fp32 accum. All splits precomputed:
// the k-loop is pure LDS + MMA. G/S/T stored as hi/lo bf16 planes by
// their producers. Unwritten tiles stay .bss zero (and are masked).
// Deterministic static schedule, no data-path atomics.

#define NN_  256
#define EE_  512
#define GRID 296

typedef unsigned u32x;
typedef unsigned short u16x;

__device__ __align__(16) u16x g_Xhi[4 * NN_ * EE_], g_Xlo[4 * NN_ * EE_];
__device__ __align__(16) u16x g_XThi[4 * EE_ * NN_], g_XTlo[4 * EE_ * NN_];
__device__ __align__(16) u16x g_Qhi[NN_ * NN_], g_Qlo[NN_ * NN_];
__device__ __align__(16) u16x g_KThi[NN_ * NN_], g_KTlo[NN_ * NN_];
__device__ __align__(16) u16x g_Ghi[4 * NN_ * NN_], g_Glo[4 * NN_ * NN_];
__device__ __align__(16) u16x g_Shi[4 * NN_ * NN_], g_Slo[4 * NN_ * NN_];
__device__ __align__(16) u16x g_Thi[4 * NN_ * NN_], g_Tlo[4 * NN_ * NN_];
__device__ __align__(16) float g_F[4 * NN_ * EE_];

__device__ __align__(128) unsigned bar_cnt[64];
__device__ __align__(128) unsigned bar_gen[64];

__device__ __forceinline__ void grid_barrier(int idx) {
    __syncthreads();
    if (threadIdx.x == 0) {
        volatile unsigned* genp = &bar_gen[idx * 8];
        const unsigned g = *genp;
        __threadfence();
        if (atomicAdd(&bar_cnt[idx * 8], 1u) == GRID - 1) {
            bar_cnt[idx * 8] = 0;
            __threadfence();
            atomicAdd(&bar_gen[idx * 8], 1u);
        } else {
            while (*genp == g) { }
        }
        __threadfence();
    }
    __syncthreads();
}

__device__ __forceinline__ u16x bhi(float v) {
    __nv_bfloat16 h = __float2bfloat16(v);
    return *(u16x*)&h;
}
__device__ __forceinline__ u16x blo(float v, u16x hb) {
    __nv_bfloat16 h = *(__nv_bfloat16*)&hb;
    __nv_bfloat16 l = __float2bfloat16(v - __bfloat162float(h));
    return *(u16x*)&l;
}

__device__ __forceinline__ void mma_bf16(float* c, const u32x* a,
                                         u32x b0, u32x b1) {
    asm("mma.sync.aligned.m16n8k16.row.col.f32.bf16.bf16.f32 "
        "{%0,%1,%2,%3},{%4,%5,%6,%7},{%8,%9},{%0,%1,%2,%3};"
        : "+f"(c[0]), "+f"(c[1]), "+f"(c[2]), "+f"(c[3])
        : "r"(a[0]), "r"(a[1]), "r"(a[2]), "r"(a[3]), "r"(b0), "r"(b1));
}

// One 32(M) x 64(N) output tile, k = [0, nst*16), operands pre-split bf16.
// 4 warps: wm = warp&1 (16-row half), wn = warp>>1 (2 x 32-col halves? no:
// wn in 0..1 -> 32-col half; each warp: 16 rows x 32 cols = 4 n8 tiles).
// MASK_A: zero A[i,k] for k>i (on staged pairs). MASK_C: zero C[i,j], j>i.
// F32OUT: store fp32 to Df, else split-store to Dhi/Dlo.
template<bool MASK_A, bool MASK_C, bool F32OUT>
__device__ __forceinline__ void tile_gemm(
    const u16x* __restrict__ Ahi, const u16x* __restrict__ Alo, int lda,
    const u16x* __restrict__ Bhi, const u16x* __restrict__ Blo, int ldb,
    u16x* __restrict__ Dhi, u16x* __restrict__ Dlo,
    float* __restrict__ Df, int ldd,
    int i0, int j0, int nst,
    u32x (*As)[2][32][12], u32x (*Bs)[2][64][12])
{
    const int tid  = threadIdx.x;
    const int lane = tid & 31;
    const int warp = tid >> 5;
    const int wm   = warp & 1;
    const int wn   = warp >> 1;
    const int g    = lane >> 2;
    const int t    = lane & 3;

    // staging assignments
    const int apl  = tid >> 6;          // A plane (0 hi, 1 lo)
    const int arow = (tid & 63) >> 1;   // 0..31
    const int ahlf = tid & 1;           // k half (8 elems)
    const int bcol = tid >> 1;          // 0..63
    const int bhlf = tid & 1;

    const u16x* Apl = apl ? Alo : Ahi;

    uint4 rA, rB[2];

    auto loadT = [&](int kg) {
        rA = *(const uint4*)&Apl[(size_t)(i0 + arow) * lda + kg + ahlf * 8];
        if (MASK_A) {
            const int i  = i0 + arow;
            const int kb = kg + ahlf * 8;
            u32x* w = (u32x*)&rA;
            #pragma unroll
            for (int m = 0; m < 4; m++) {
                const int kk = kb + 2 * m;
                if (kk > i)          w[m] = 0u;
                else if (kk + 1 > i) w[m] &= 0xFFFFu;
            }
        }
        rB[0] = *(const uint4*)&Bhi[(size_t)(j0 + bcol) * ldb + kg + bhlf * 8];
        rB[1] = *(const uint4*)&Blo[(size_t)(j0 + bcol) * ldb + kg + bhlf * 8];
    };
    auto stageT = [&](int buf) {
        *(uint4*)&As[buf][apl][arow][ahlf * 4] = rA;
        *(uint4*)&Bs[buf][0][bcol][bhlf * 4] = rB[0];
        *(uint4*)&Bs[buf][1][bcol][bhlf * 4] = rB[1];
    };

    float acc[4][4] = {};

    auto compute = [&](int buf) {
        u32x ah[4], al[4];
        const int ar = wm * 16 + g;
        ah[0] = As[buf][0][ar][t];     ah[1] = As[buf][0][ar + 8][t];
        ah[2] = As[buf][0][ar][t + 4]; ah[3] = As[buf][0][ar + 8][t + 4];
        al[0] = As[buf][1][ar][t];     al[1] = As[buf][1][ar + 8][t];
        al[2] = As[buf][1][ar][t + 4]; al[3] = As[buf][1][ar + 8][t + 4];
        #pragma unroll
        for (int u = 0; u < 4; u++) {
            const int bc = wn * 32 + u * 8 + g;
            const u32x bh0 = Bs[buf][0][bc][t], bh1 = Bs[buf][0][bc][t + 4];
            const u32x bl0 = Bs[buf][1][bc][t], bl1 = Bs[buf][1][bc][t + 4];
            mma_bf16(acc[u], ah, bh0, bh1);
            mma_bf16(acc[u], ah, bl0, bl1);
            mma_bf16(acc[u], al, bh0, bh1);
        }
    };

    loadT(0);
    stageT(0);
    __syncthreads();
    int buf = 0;
    #pragma unroll 1
    for (int s = 0; s < nst; s++) {
        if (s + 1 < nst) loadT((s + 1) * 16);
        compute(buf);
        if (s + 1 < nst) {
            stageT(buf ^ 1);
            __syncthreads();
            buf ^= 1;
        }
    }

    #pragma unroll
    for (int u = 0; u < 4; u++) {
        const int jb = j0 + wn * 32 + u * 8 + 2 * t;
        #pragma unroll
        for (int h = 0; h < 2; h++) {
            const int i = i0 + wm * 16 + g + h * 8;
            float c0 = acc[u][2 * h], c1 = acc[u][2 * h + 1];
            if (MASK_C) {
                if (jb > i)     c0 = 0.f;
                if (jb + 1 > i) c1 = 0.f;
            }
            if (F32OUT) {
                *(float2*)&Df[(size_t)i * ldd + jb] = make_float2(c0, c1);
            } else {
                const u16x h0 = bhi(c0), h1 = bhi(c1);
                const u16x l0 = blo(c0, h0), l1 = blo(c1, h1);
                *(u32x*)&Dhi[(size_t)i * ldd + jb] = (u32x)h0 | ((u32x)h1 << 16);
                *(u32x*)&Dlo[(size_t)i * ldd + jb] = (u32x)l0 | ((u32x)l1 << 16);
            }
        }
    }
    __syncthreads();   // smem reuse by next job
}

// 20 lower 32x64 tiles (r 0..7, c 0..3 with c*64 <= r*32+31)
__constant__ int t20_r[20] = {0,1,2,2,3,3,4,4,4,5,5,5,6,6,6,6,7,7,7,7};
__constant__ int t20_c[20] = {0,0,0,1,0,1,0,1,2,0,1,2,0,1,2,3,0,1,2,3};

__global__ __launch_bounds__(128, 4)
void replicator_bf16(const float* __restrict__ X,
                     const float* __restrict__ Qw,
                     const float* __restrict__ Kw,
                     float* __restrict__ out)
{
    __shared__ u32x As[2][2][32][12];
    __shared__ u32x Bs[2][2][64][12];
    __shared__ float red[4];

    const int tid = threadIdx.x;

    // ================= P0: pre-split conversions =================
    // X -> Xhi/Xlo (row-major) and XT (transposed)
    for (int idx = blockIdx.x * 128 + tid; idx < 4 * NN_ * EE_ / 4;
         idx += GRID * 128) {
        const float4 v = ((const float4*)X)[idx];
        const int e  = (idx & 127) * 4;
        const int bn = idx >> 7;
        const int b  = bn >> 8, n = bn & 255;
        const float vv[4] = {v.x, v.y, v.z, v.w};
        u16x hh[4], ll[4];
        #pragma unroll
        for (int j = 0; j < 4; j++) { hh[j] = bhi(vv[j]); ll[j] = blo(vv[j], hh[j]); }
        *(u32x*)&g_Xhi[(size_t)bn * EE_ + e]     = (u32x)hh[0] | ((u32x)hh[1] << 16);
        *(u32x*)&g_Xhi[(size_t)bn * EE_ + e + 2] = (u32x)hh[2] | ((u32x)hh[3] << 16);
        *(u32x*)&g_Xlo[(size_t)bn * EE_ + e]     = (u32x)ll[0] | ((u32x)ll[1] << 16);
        *(u32x*)&g_Xlo[(size_t)bn * EE_ + e + 2] = (u32x)ll[2] | ((u32x)ll[3] << 16);
        const size_t xb = (size_t)b * EE_ * NN_;
        #pragma unroll
        for (int j = 0; j < 4; j++) {
            g_XThi[xb + (size_t)(e + j) * NN_ + n] = hh[j];
            g_XTlo[xb + (size_t)(e + j) * NN_ + n] = ll[j];
        }
    }
    // Qw -> Qhi/Qlo (as-is); Kw -> KwT hi/lo (transposed)
    for (int idx = blockIdx.x * 128 + tid; idx < NN_ * NN_ / 4;
         idx += GRID * 128) {
        const int c = (idx & 63) * 4;
        const int r = idx >> 6;
        const float4 q = ((const float4*)Qw)[idx];
        const float qv[4] = {q.x, q.y, q.z, q.w};
        u16x qh[4], ql[4];
        #pragma unroll
        for (int j = 0; j < 4; j++) { qh[j] = bhi(qv[j]); ql[j] = blo(qv[j], qh[j]); }
        *(u32x*)&g_Qhi[(size_t)r * NN_ + c]     = (u32x)qh[0] | ((u32x)qh[1] << 16);
        *(u32x*)&g_Qhi[(size_t)r * NN_ + c + 2] = (u32x)qh[2] | ((u32x)qh[3] << 16);
        *(u32x*)&g_Qlo[(size_t)r * NN_ + c]     = (u32x)ql[0] | ((u32x)ql[1] << 16);
        *(u32x*)&g_Qlo[(size_t)r * NN_ + c + 2] = (u32x)ql[2] | ((u32x)ql[3] << 16);
        const float4 k = ((const float4*)Kw)[idx];
        const float kv[4] = {k.x, k.y, k.z, k.w};
        #pragma unroll
        for (int j = 0; j < 4; j++) {
            const u16x kh = bhi(kv[j]);
            g_KThi[(size_t)(c + j) * NN_ + r] = kh;
            g_KTlo[(size_t)(c + j) * NN_ + r] = blo(kv[j], kh);
        }
    }
    grid_barrier(0);

    // ================= P1: G = X X^T (80 jobs, K=512) =================
    for (int job = blockIdx.x; job < 80; job += GRID) {
        const int b = job / 20;
        const int e = job - b * 20;
        const size_t xo = (size_t)b * NN_ * EE_;
        const size_t go = (size_t)b * NN_ * NN_;
        tile_gemm<false, false, false>(
            g_Xhi + xo, g_Xlo + xo, EE_,
            g_Xhi + xo, g_Xlo + xo, EE_,
            g_Ghi + go, g_Glo + go, nullptr, NN_,
            t20_r[e] * 32, t20_c[e] * 64, 32, As, Bs);
    }
    grid_barrier(1);

    // ================= P2: S = L( L(G) Kw )  (80 jobs) =================
    for (int job = blockIdx.x; job < 80; job += GRID) {
        const int b = job / 20;
        const int e = job - b * 20;
        const size_t go = (size_t)b * NN_ * NN_;
        tile_gemm<true, true, false>(
            g_Ghi + go, g_Glo + go, NN_,
            g_KThi, g_KTlo, NN_,
            g_Shi + go, g_Slo + go, nullptr, NN_,
            t20_r[e] * 32, t20_c[e] * 64, 2 * t20_r[e] + 2, As, Bs);
    }
    grid_barrier(2);

    // ================= P3: T = L( S Qw^T )  (80 jobs) =================
    for (int job = blockIdx.x; job < 80; job += GRID) {
        const int b = job / 20;
        const int e = job - b * 20;
        const size_t go = (size_t)b * NN_ * NN_;
        tile_gemm<false, true, false>(
            g_Shi + go, g_Slo + go, NN_,
            g_Qhi, g_Qlo, NN_,
            g_Thi + go, g_Tlo + go, nullptr, NN_,
            t20_r[e] * 32, t20_c[e] * 64, 2 * t20_r[e] + 2, As, Bs);
    }
    grid_barrier(3);

    // ================= P4: F = T X  (256 jobs, fp32 out) =================
    for (int job = blockIdx.x; job < 256; job += GRID) {
        const int b  = job / 64;
        const int rm = job - b * 64;
        const int r  = rm >> 3;
        const int et = rm & 7;
        const size_t go = (size_t)b * NN_ * NN_;
        const size_t xo = (size_t)b * EE_ * NN_;
        tile_gemm<false, false, true>(
            g_Thi + go, g_Tlo + go, NN_,
            g_XThi + xo, g_XTlo + xo, NN_,
            nullptr, nullptr, g_F + (size_t)b * NN_ * EE_, EE_,
            r * 32, et * 64, 2 * r + 2, As, Bs);
    }
    grid_barrier(4);

    // ================= P5: epilogue (1024 rows) =================
    for (int job = blockIdx.x; job < 1024; job += GRID) {
        const size_t base = (size_t)job * EE_;

        float4 x = *(const float4*)&X[base + tid * 4];
        float4 f = *(const float4*)&g_F[base + tid * 4];

        float sum = x.x * f.x + x.y * f.y + x.z * f.z + x.w * f.w;
        #pragma unroll
        for (int o = 16; o; o >>= 1)
            sum += __shfl_xor_sync(0xffffffffu, sum, o);

        if ((tid & 31) == 0) red[tid >> 5] = sum;
        __syncthreads();
        const float avg = red[0] + red[1] + red[2] + red[3];

        float4 o;
        o.x = x.x * (1.f + f.x - avg);
        o.y = x.y * (1.f + f.y - avg);
        o.z = x.z * (1.f + f.z - avg);
        o.w = x.w * (1.f + f.w - avg);
        *(float4*)&out[base + tid * 4] = o;
        __syncthreads();
    }
}

extern "C" void kernel_launch(void* const* d_in, const int* in_sizes, int n_in,
                              void* d_out, int out_size)
{
    const float* X  = (const float*)d_in[0];   // (4,256,512)
    const float* Qw = (const float*)d_in[1];   // (256,256)
    const float* Kw = (const float*)d_in[2];   // (256,256)
    float* out = (float*)d_out;                // (4,256,512)

    replicator_bf16<<<GRID, 128>>>(X, Qw, Kw, out);
}

// round 12
// speedup vs baseline: 1.4876x; 1.4876x over previous
#include <cuda_runtime.h>
#include <cuda_bf16.h>
#include <cstdint>
#include <cstddef>

// B=4, N=256, E=512. Persistent kernel: 296 CTAs (2/SM forced) x 128 threads.
// Static schedule, grid barriers between phases:
//   P1: G = tril( X X^T )        (32x64 lower tiles, K=512, 80 jobs)
//   P2: S = tril( G Kw )         (80 jobs, K = (r+1)*32; G pre-masked)
//   P3: T = tril( S Qw^T )       (80 jobs)
//   P4: F = T X                  (256 jobs, fp32)
//   P5: out = x*(1 + f - x.f)    (1024 jobs)
// Masks applied at STORE time only (G/S/T stored tril-masked), so every
// consumer GEMM is unmasked. Engine: mma.sync m16n8k8 tf32, 2-way split
// (D += Ah*Bh + Ah*Bl + Al*Bh), fp32 accum (err ~2^-22).
// Staging: cp.async.cg, 4 stages in flight, 5 smem slots -> L2 latency
// fully hidden by compute. Deterministic static schedule.

#define NN_  256
#define EE_  512
#define GRID 296
#define PIPE  4
#define SLOTS 5

__device__ __align__(16) float g_G[4 * NN_ * NN_];
__device__ __align__(16) float g_S[4 * NN_ * NN_];
__device__ __align__(16) float g_T[4 * NN_ * NN_];
__device__ __align__(16) float g_F[4 * NN_ * EE_];

__device__ __align__(128) unsigned bar_cnt[64];
__device__ __align__(128) unsigned bar_gen[64];

__device__ __forceinline__ void grid_barrier(int idx) {
    __syncthreads();
    if (threadIdx.x == 0) {
        volatile unsigned* genp = &bar_gen[idx * 8];
        const unsigned g = *genp;
        __threadfence();
        if (atomicAdd(&bar_cnt[idx * 8], 1u) == GRID - 1) {
            bar_cnt[idx * 8] = 0;
            __threadfence();
            atomicAdd(&bar_gen[idx * 8], 1u);
        } else {
            while (*genp == g) { }
        }
        __threadfence();
    }
    __syncthreads();
}

__device__ __forceinline__ unsigned f2tf(float x) {
    unsigned r;
    asm("cvt.rna.tf32.f32 %0, %1;" : "=r"(r) : "f"(x));
    return r;
}
__device__ __forceinline__ void mma_tf32(float* c, const unsigned* a,
                                         unsigned b0, unsigned b1) {
    asm("mma.sync.aligned.m16n8k8.row.col.f32.tf32.tf32.f32 "
        "{%0,%1,%2,%3},{%4,%5,%6,%7},{%8,%9},{%0,%1,%2,%3};"
        : "+f"(c[0]), "+f"(c[1]), "+f"(c[2]), "+f"(c[3])
        : "r"(a[0]), "r"(a[1]), "r"(a[2]), "r"(a[3]), "r"(b0), "r"(b1));
}

__device__ __forceinline__ void cp16(void* sdst, const void* gsrc) {
    const unsigned d = (unsigned)__cvta_generic_to_shared(sdst);
    asm volatile("cp.async.cg.shared.global [%0], [%1], 16;"
                 :: "r"(d), "l"(gsrc));
}
#define CP_COMMIT() asm volatile("cp.async.commit_group;")
#define CP_WAIT3()  asm volatile("cp.async.wait_group 3;")

// One 32(M) x 64(N) output tile, k = [0, nst*16).
// A row-major [i][k] (lda). NT: B[j][k] row-major (ldb), else B[k][j].
// MASK_C: zero C[i][j] for j > i at store. C fp32 (ldc).
// 4 warps: wm = warp&1 (16-row half), wn = warp>>1 (32-col half);
// per warp 1 m16 x 4 n8 mma tiles, tf32 2-way split (3 mma each).
// cp.async pipeline: PIPE=4 in flight, SLOTS=5 smem slots.
template<bool NT, bool MASK_C>
__device__ __forceinline__ void tile_gemm(
    const float* __restrict__ A, int lda,
    const float* __restrict__ B, int ldb,
    float* __restrict__ C, int ldc,
    int i0, int j0, int nst,
    float (*As)[32 * 20], float (*Bs)[1280])
{
    const int tid  = threadIdx.x;
    const int lane = tid & 31;
    const int warp = tid >> 5;
    const int wm   = warp & 1;
    const int wn   = warp >> 1;
    const int g    = lane >> 2;
    const int t    = lane & 3;

    const int arow = tid >> 2;            // 0..31
    const int ac4  = (tid & 3) << 2;      // 0,4,8,12

    auto issue_stage = [&](int s) {
        const int kg   = s * 16;
        const int slot = s % SLOTS;
        cp16(&As[slot][arow * 20 + ac4],
             &A[(size_t)(i0 + arow) * lda + kg + ac4]);
        #pragma unroll
        for (int h = 0; h < 2; h++) {
            const int c = tid + h * 128;
            if (NT) {
                const int row = c >> 2, cc = (c & 3) << 2;     // 64 x 16
                cp16(&Bs[slot][row * 20 + cc],
                     &B[(size_t)(j0 + row) * ldb + kg + cc]);
            } else {
                const int row = c >> 4, cc = (c & 15) << 2;    // 16 x 64
                cp16(&Bs[slot][row * 72 + cc],
                     &B[(size_t)(kg + row) * ldb + j0 + cc]);
            }
        }
    };

    float acc[4][4] = {};

    #pragma unroll
    for (int s = 0; s < PIPE; s++) {
        if (s < nst) issue_stage(s);
        CP_COMMIT();
    }

    #pragma unroll 1
    for (int s = 0; s < nst; s++) {
        CP_WAIT3();
        __syncthreads();
        if (s + PIPE < nst) issue_stage(s + PIPE);   // slot (s+4)%5 == (s-1)%5: free
        CP_COMMIT();

        const float* Asl = As[s % SLOTS];
        const float* Bsl = Bs[s % SLOTS];
        #pragma unroll
        for (int kk = 0; kk < 16; kk += 8) {
            unsigned ahi[4], alo[4];
            #pragma unroll
            for (int r = 0; r < 4; r++) {
                const int row = wm * 16 + g + ((r & 1) << 3);
                const int kc  = kk + t + ((r >> 1) << 2);
                const float v = Asl[row * 20 + kc];
                const unsigned hb = f2tf(v);
                ahi[r] = hb;
                alo[r] = f2tf(v - __uint_as_float(hb));
            }
            #pragma unroll
            for (int u = 0; u < 4; u++) {
                const int col = wn * 32 + u * 8 + g;
                const float v0 = NT ? Bsl[col * 20 + kk + t]
                                    : Bsl[(kk + t) * 72 + col];
                const float v1 = NT ? Bsl[col * 20 + kk + t + 4]
                                    : Bsl[(kk + t + 4) * 72 + col];
                const unsigned bh0 = f2tf(v0), bh1 = f2tf(v1);
                const unsigned bl0 = f2tf(v0 - __uint_as_float(bh0));
                const unsigned bl1 = f2tf(v1 - __uint_as_float(bh1));
                mma_tf32(acc[u], ahi, bh0, bh1);
                mma_tf32(acc[u], ahi, bl0, bl1);
                mma_tf32(acc[u], alo, bh0, bh1);
            }
        }
    }

    #pragma unroll
    for (int u = 0; u < 4; u++) {
        const int jb = j0 + wn * 32 + u * 8 + 2 * t;
        #pragma unroll
        for (int h = 0; h < 2; h++) {
            const int i = i0 + wm * 16 + g + h * 8;
            float c0 = acc[u][2 * h], c1 = acc[u][2 * h + 1];
            if (MASK_C) {
                if (jb > i)     c0 = 0.f;
                if (jb + 1 > i) c1 = 0.f;
            }
            *(float2*)&C[(size_t)i * ldc + jb] = make_float2(c0, c1);
        }
    }
    __syncthreads();   // protect smem slots before next job's prologue
}

// 20 lower 32x64 tiles per 256x256 (r 0..7; c*64 <= r*32+31)
__constant__ int t20_r[20] = {0,1,2,2,3,3,4,4,4,5,5,5,6,6,6,6,7,7,7,7};
__constant__ int t20_c[20] = {0,0,0,1,0,1,0,1,2,0,1,2,0,1,2,3,0,1,2,3};

__global__ __launch_bounds__(128, 2)
void replicator_async(const float* __restrict__ X,
                      const float* __restrict__ Qw,
                      const float* __restrict__ Kw,
                      float* __restrict__ out)
{
    __shared__ float As[SLOTS][32 * 20];   // 12.8 KB
    __shared__ float Bs[SLOTS][1280];      // 25.6 KB
    __shared__ float red[4];

    const int tid = threadIdx.x;
    const size_t sX = (size_t)NN_ * EE_;
    const size_t sG = (size_t)NN_ * NN_;

    // ---- P1: G = tril(X X^T), 80 jobs, K=512 (32 stages)
    for (int job = blockIdx.x; job < 80; job += GRID) {
        const int b = job / 20;
        const int e = job - b * 20;
        tile_gemm<true, true>(
            X + b * sX, EE_, X + b * sX, EE_, g_G + b * sG, NN_,
            t20_r[e] * 32, t20_c[e] * 64, 32, As, Bs);
    }
    grid_barrier(0);

    // ---- P2: S = tril(G Kw), 80 jobs, nst = 2r+2 (G pre-masked)
    for (int job = blockIdx.x; job < 80; job += GRID) {
        const int b = job / 20;
        const int e = job - b * 20;
        tile_gemm<false, true>(
            g_G + b * sG, NN_, Kw, NN_, g_S + b * sG, NN_,
            t20_r[e] * 32, t20_c[e] * 64, 2 * t20_r[e] + 2, As, Bs);
    }
    grid_barrier(1);

    // ---- P3: T = tril(S Qw^T), 80 jobs
    for (int job = blockIdx.x; job < 80; job += GRID) {
        const int b = job / 20;
        const int e = job - b * 20;
        tile_gemm<true, true>(
            g_S + b * sG, NN_, Qw, NN_, g_T + b * sG, NN_,
            t20_r[e] * 32, t20_c[e] * 64, 2 * t20_r[e] + 2, As, Bs);
    }
    grid_barrier(2);

    // ---- P4: F = T X, 256 jobs (8 row-bands x 8 e-tiles x 4 batch)
    for (int job = blockIdx.x; job < 256; job += GRID) {
        const int b  = job / 64;
        const int rm = job - b * 64;
        const int r  = rm >> 3;
        const int et = rm & 7;
        tile_gemm<false, false>(
            g_T + b * sG, NN_, X + b * sX, EE_, g_F + b * sX, EE_,
            r * 32, et * 64, 2 * r + 2, As, Bs);
    }
    grid_barrier(3);

    // ---- P5: epilogue, 1024 rows
    for (int job = blockIdx.x; job < 1024; job += GRID) {
        const size_t base = (size_t)job * EE_;

        float4 x = *(const float4*)&X[base + tid * 4];
        float4 f = *(const float4*)&g_F[base + tid * 4];

        float sum = x.x * f.x + x.y * f.y + x.z * f.z + x.w * f.w;
        #pragma unroll
        for (int o = 16; o; o >>= 1)
            sum += __shfl_xor_sync(0xffffffffu, sum, o);

        if ((tid & 31) == 0) red[tid >> 5] = sum;
        __syncthreads();
        const float avg = red[0] + red[1] + red[2] + red[3];

        float4 o;
        o.x = x.x * (1.f + f.x - avg);
        o.y = x.y * (1.f + f.y - avg);
        o.z = x.z * (1.f + f.z - avg);
        o.w = x.w * (1.f + f.w - avg);
        *(float4*)&out[base + tid * 4] = o;
        __syncthreads();
    }
}

extern "C" void kernel_launch(void* const* d_in, const int* in_sizes, int n_in,
                              void* d_out, int out_size)
{
    const float* X  = (const float*)d_in[0];   // (4,256,512)
    const float* Qw = (const float*)d_in[1];   // (256,256)
    const float* Kw = (const float*)d_in[2];   // (256,256)
    float* out = (float*)d_out;                // (4,256,512)

    replicator_async<<<GRID, 128>>>(X, Qw, Kw, out);
}

// round 13
// speedup vs baseline: 1.4963x; 1.0059x over previous
#include <cuda_runtime.h>
#include <cuda_bf16.h>
#include <cstdint>
#include <cstddef>

// B=4, N=256, E=512. Persistent kernel: 296 CTAs (2/SM forced) x 128 threads.
// Static schedule, grid barriers between phases:
//   P1: G = tril( X X^T )        (32x64 lower tiles, K=512, 80 jobs)
//   P2: S = tril( G Kw )         (80 jobs, K = (r+1)*32; G pre-masked)
//   P3: T = tril( S Qw^T )       (80 jobs)
//   P4: F = T X                  (256 jobs, fp32)
//   P5: out = x*(1 + f - x.f)    (1024 jobs)
// Masks applied at STORE time only (G/S/T stored tril-masked), so every
// consumer GEMM is unmasked. Engine: mma.sync m16n8k8 tf32, 2-way split
// (D += Ah*Bh + Ah*Bl + Al*Bh), fp32 accum (err ~2^-22).
// Staging: cp.async.cg, 4 stages in flight, 5 smem slots -> L2 latency
// fully hidden by compute. Deterministic static schedule.

#define NN_  256
#define EE_  512
#define GRID 296
#define PIPE  4
#define SLOTS 5

__device__ __align__(16) float g_G[4 * NN_ * NN_];
__device__ __align__(16) float g_S[4 * NN_ * NN_];
__device__ __align__(16) float g_T[4 * NN_ * NN_];
__device__ __align__(16) float g_F[4 * NN_ * EE_];

__device__ __align__(128) unsigned bar_cnt[64];
__device__ __align__(128) unsigned bar_gen[64];

__device__ __forceinline__ void grid_barrier(int idx) {
    __syncthreads();
    if (threadIdx.x == 0) {
        volatile unsigned* genp = &bar_gen[idx * 8];
        const unsigned g = *genp;
        __threadfence();
        if (atomicAdd(&bar_cnt[idx * 8], 1u) == GRID - 1) {
            bar_cnt[idx * 8] = 0;
            __threadfence();
            atomicAdd(&bar_gen[idx * 8], 1u);
        } else {
            while (*genp == g) { }
        }
        __threadfence();
    }
    __syncthreads();
}

__device__ __forceinline__ unsigned f2tf(float x) {
    unsigned r;
    asm("cvt.rna.tf32.f32 %0, %1;" : "=r"(r) : "f"(x));
    return r;
}
__device__ __forceinline__ void mma_tf32(float* c, const unsigned* a,
                                         unsigned b0, unsigned b1) {
    asm("mma.sync.aligned.m16n8k8.row.col.f32.tf32.tf32.f32 "
        "{%0,%1,%2,%3},{%4,%5,%6,%7},{%8,%9},{%0,%1,%2,%3};"
        : "+f"(c[0]), "+f"(c[1]), "+f"(c[2]), "+f"(c[3])
        : "r"(a[0]), "r"(a[1]), "r"(a[2]), "r"(a[3]), "r"(b0), "r"(b1));
}

__device__ __forceinline__ void cp16(void* sdst, const void* gsrc) {
    const unsigned d = (unsigned)__cvta_generic_to_shared(sdst);
    asm volatile("cp.async.cg.shared.global [%0], [%1], 16;"
                 :: "r"(d), "l"(gsrc));
}
#define CP_COMMIT() asm volatile("cp.async.commit_group;")
#define CP_WAIT3()  asm volatile("cp.async.wait_group 3;")

// One 32(M) x 64(N) output tile, k = [0, nst*16).
// A row-major [i][k] (lda). NT: B[j][k] row-major (ldb), else B[k][j].
// MASK_C: zero C[i][j] for j > i at store. C fp32 (ldc).
// 4 warps: wm = warp&1 (16-row half), wn = warp>>1 (32-col half);
// per warp 1 m16 x 4 n8 mma tiles, tf32 2-way split (3 mma each).
// cp.async pipeline: PIPE=4 in flight, SLOTS=5 smem slots.
template<bool NT, bool MASK_C>
__device__ __forceinline__ void tile_gemm(
    const float* __restrict__ A, int lda,
    const float* __restrict__ B, int ldb,
    float* __restrict__ C, int ldc,
    int i0, int j0, int nst,
    float (*As)[32 * 20], float (*Bs)[1280])
{
    const int tid  = threadIdx.x;
    const int lane = tid & 31;
    const int warp = tid >> 5;
    const int wm   = warp & 1;
    const int wn   = warp >> 1;
    const int g    = lane >> 2;
    const int t    = lane & 3;

    const int arow = tid >> 2;            // 0..31
    const int ac4  = (tid & 3) << 2;      // 0,4,8,12

    auto issue_stage = [&](int s) {
        const int kg   = s * 16;
        const int slot = s % SLOTS;
        cp16(&As[slot][arow * 20 + ac4],
             &A[(size_t)(i0 + arow) * lda + kg + ac4]);
        #pragma unroll
        for (int h = 0; h < 2; h++) {
            const int c = tid + h * 128;
            if (NT) {
                const int row = c >> 2, cc = (c & 3) << 2;     // 64 x 16
                cp16(&Bs[slot][row * 20 + cc],
                     &B[(size_t)(j0 + row) * ldb + kg + cc]);
            } else {
                const int row = c >> 4, cc = (c & 15) << 2;    // 16 x 64
                cp16(&Bs[slot][row * 72 + cc],
                     &B[(size_t)(kg + row) * ldb + j0 + cc]);
            }
        }
    };

    float acc[4][4] = {};

    #pragma unroll
    for (int s = 0; s < PIPE; s++) {
        if (s < nst) issue_stage(s);
        CP_COMMIT();
    }

    #pragma unroll 1
    for (int s = 0; s < nst; s++) {
        CP_WAIT3();
        __syncthreads();
        if (s + PIPE < nst) issue_stage(s + PIPE);   // slot (s+4)%5 == (s-1)%5: free
        CP_COMMIT();

        const float* Asl = As[s % SLOTS];
        const float* Bsl = Bs[s % SLOTS];
        #pragma unroll
        for (int kk = 0; kk < 16; kk += 8) {
            unsigned ahi[4], alo[4];
            #pragma unroll
            for (int r = 0; r < 4; r++) {
                const int row = wm * 16 + g + ((r & 1) << 3);
                const int kc  = kk + t + ((r >> 1) << 2);
                const float v = Asl[row * 20 + kc];
                const unsigned hb = f2tf(v);
                ahi[r] = hb;
                alo[r] = f2tf(v - __uint_as_float(hb));
            }
            #pragma unroll
            for (int u = 0; u < 4; u++) {
                const int col = wn * 32 + u * 8 + g;
                const float v0 = NT ? Bsl[col * 20 + kk + t]
                                    : Bsl[(kk + t) * 72 + col];
                const float v1 = NT ? Bsl[col * 20 + kk + t + 4]
                                    : Bsl[(kk + t + 4) * 72 + col];
                const unsigned bh0 = f2tf(v0), bh1 = f2tf(v1);
                const unsigned bl0 = f2tf(v0 - __uint_as_float(bh0));
                const unsigned bl1 = f2tf(v1 - __uint_as_float(bh1));
                mma_tf32(acc[u], ahi, bh0, bh1);
                mma_tf32(acc[u], ahi, bl0, bl1);
                mma_tf32(acc[u], alo, bh0, bh1);
            }
        }
    }

    #pragma unroll
    for (int u = 0; u < 4; u++) {
        const int jb = j0 + wn * 32 + u * 8 + 2 * t;
        #pragma unroll
        for (int h = 0; h < 2; h++) {
            const int i = i0 + wm * 16 + g + h * 8;
            float c0 = acc[u][2 * h], c1 = acc[u][2 * h + 1];
            if (MASK_C) {
                if (jb > i)     c0 = 0.f;
                if (jb + 1 > i) c1 = 0.f;
            }
            *(float2*)&C[(size_t)i * ldc + jb] = make_float2(c0, c1);
        }
    }
    __syncthreads();   // protect smem slots before next job's prologue
}

// 20 lower 32x64 tiles per 256x256 (r 0..7; c*64 <= r*32+31)
__constant__ int t20_r[20] = {0,1,2,2,3,3,4,4,4,5,5,5,6,6,6,6,7,7,7,7};
__constant__ int t20_c[20] = {0,0,0,1,0,1,0,1,2,0,1,2,0,1,2,3,0,1,2,3};

__global__ __launch_bounds__(128, 2)
void replicator_async(const float* __restrict__ X,
                      const float* __restrict__ Qw,
                      const float* __restrict__ Kw,
                      float* __restrict__ out)
{
    __shared__ float As[SLOTS][32 * 20];   // 12.8 KB
    __shared__ float Bs[SLOTS][1280];      // 25.6 KB
    __shared__ float red[4];

    const int tid = threadIdx.x;
    const size_t sX = (size_t)NN_ * EE_;
    const size_t sG = (size_t)NN_ * NN_;

    // ---- P1: G = tril(X X^T), 80 jobs, K=512 (32 stages)
    for (int job = blockIdx.x; job < 80; job += GRID) {
        const int b = job / 20;
        const int e = job - b * 20;
        tile_gemm<true, true>(
            X + b * sX, EE_, X + b * sX, EE_, g_G + b * sG, NN_,
            t20_r[e] * 32, t20_c[e] * 64, 32, As, Bs);
    }
    grid_barrier(0);

    // ---- P2: S = tril(G Kw), 80 jobs, nst = 2r+2 (G pre-masked)
    for (int job = blockIdx.x; job < 80; job += GRID) {
        const int b = job / 20;
        const int e = job - b * 20;
        tile_gemm<false, true>(
            g_G + b * sG, NN_, Kw, NN_, g_S + b * sG, NN_,
            t20_r[e] * 32, t20_c[e] * 64, 2 * t20_r[e] + 2, As, Bs);
    }
    grid_barrier(1);

    // ---- P3: T = tril(S Qw^T), 80 jobs
    for (int job = blockIdx.x; job < 80; job += GRID) {
        const int b = job / 20;
        const int e = job - b * 20;
        tile_gemm<true, true>(
            g_S + b * sG, NN_, Qw, NN_, g_T + b * sG, NN_,
            t20_r[e] * 32, t20_c[e] * 64, 2 * t20_r[e] + 2, As, Bs);
    }
    grid_barrier(2);

    // ---- P4: F = T X, 256 jobs (8 row-bands x 8 e-tiles x 4 batch)
    for (int job = blockIdx.x; job < 256; job += GRID) {
        const int b  = job / 64;
        const int rm = job - b * 64;
        const int r  = rm >> 3;
        const int et = rm & 7;
        tile_gemm<false, false>(
            g_T + b * sG, NN_, X + b * sX, EE_, g_F + b * sX, EE_,
            r * 32, et * 64, 2 * r + 2, As, Bs);
    }
    grid_barrier(3);

    // ---- P5: epilogue, 1024 rows
    for (int job = blockIdx.x; job < 1024; job += GRID) {
        const size_t base = (size_t)job * EE_;

        float4 x = *(const float4*)&X[base + tid * 4];
        float4 f = *(const float4*)&g_F[base + tid * 4];

        float sum = x.x * f.x + x.y * f.y + x.z * f.z + x.w * f.w;
        #pragma unroll
        for (int o = 16; o; o >>= 1)
            sum += __shfl_xor_sync(0xffffffffu, sum, o);

        if ((tid & 31) == 0) red[tid >> 5] = sum;
        __syncthreads();
        const float avg = red[0] + red[1] + red[2] + red[3];

        float4 o;
        o.x = x.x * (1.f + f.x - avg);
        o.y = x.y * (1.f + f.y - avg);
        o.z = x.z * (1.f + f.z - avg);
        o.w = x.w * (1.f + f.w - avg);
        *(float4*)&out[base + tid * 4] = o;
        __syncthreads();
    }
}

extern "C" void kernel_launch(void* const* d_in, const int* in_sizes, int n_in,
                              void* d_out, int out_size)
{
    const float* X  = (const float*)d_in[0];   // (4,256,512)
    const float* Qw = (const float*)d_in[1];   // (256,256)
    const float* Kw = (const float*)d_in[2];   // (256,256)
    float* out = (float*)d_out;                // (4,256,512)

    replicator_async<<<GRID, 128>>>(X, Qw, Kw, out);
}